// round 13
// baseline (speedup 1.0000x reference)
#include <cuda_runtime.h>
#include <cuda_bf16.h>
#include <math.h>
#include <stdint.h>

// ---------------------------------------------------------------------------
// Problem constants
// ---------------------------------------------------------------------------
#define BATCH   2
#define CH      192
#define DIM     32
#define SPAT    (DIM*DIM*DIM)      // 32768
#define HID     768
#define KS      7
#define KV      343
#define NCELLS  1024               // 2 * 8*8*8
#define CELLTOK 64                 // 4*4*4

// ---------------------------------------------------------------------------
// Device scratch (static globals -- no runtime allocation)
// ---------------------------------------------------------------------------
__device__ int    g_cellList[NCELLS];
__device__ int    g_cellCount;
__device__ float  g_yc[(size_t)NCELLS * CELLTOK * CH];    // compacted conv out
__device__ float2 g_stats[(size_t)NCELLS * CELLTOK];      // (mu, rstd) per token
__device__ float  g_h [(size_t)NCELLS * CELLTOK * HID];   // hidden activations
__device__ float  g_w1r[CH * HID];                        // tf32-rounded w1
__device__ float  g_w2r[HID * CH];                        // tf32-rounded w2

// ---------------------------------------------------------------------------
// Helpers
// ---------------------------------------------------------------------------
__device__ __forceinline__ float2 ffma2(float2 a, float2 b, float2 c) {
    union U { float2 f; unsigned long long u; };
    U A, B, C, D;
    A.f = a; B.f = b; C.f = c;
    asm("fma.rn.f32x2 %0, %1, %2, %3;" : "=l"(D.u) : "l"(A.u), "l"(B.u), "l"(C.u));
    return D.f;
}

__device__ __forceinline__ float tf32r(float x) {
    unsigned int u;
    asm("cvt.rna.tf32.f32 %0, %1;" : "=r"(u) : "f"(x));
    return __uint_as_float(u);
}

// mma.sync m16n8k8 tf32: d += a * b   (mapping verified by passing rounds)
__device__ __forceinline__ void mma_tf32(float* d, const float* a, float b0, float b1) {
    asm volatile(
        "mma.sync.aligned.m16n8k8.row.col.f32.tf32.tf32.f32 "
        "{%0,%1,%2,%3}, {%4,%5,%6,%7}, {%8,%9}, {%0,%1,%2,%3};"
        : "+f"(d[0]), "+f"(d[1]), "+f"(d[2]), "+f"(d[3])
        : "r"(__float_as_uint(a[0])), "r"(__float_as_uint(a[1])),
          "r"(__float_as_uint(a[2])), "r"(__float_as_uint(a[3])),
          "r"(__float_as_uint(b0)),   "r"(__float_as_uint(b1)));
}

__device__ __forceinline__ float gelu_exact(float x) {
    return 0.5f * x * (1.0f + erff(x * 0.70710678118654752f));
}

__device__ __forceinline__ void cp_async16(void* smem_dst, const void* gmem_src) {
    unsigned s = (unsigned)__cvta_generic_to_shared(smem_dst);
    asm volatile("cp.async.cg.shared.global [%0], [%1], 16;\n" :: "r"(s), "l"(gmem_src));
}
#define CP_COMMIT() asm volatile("cp.async.commit_group;\n" ::: "memory")
#define CP_WAIT1()  asm volatile("cp.async.wait_group 1;\n" ::: "memory")

// ---------------------------------------------------------------------------
// Kernel 0a: build compacted active-cell list (dtype-sniffing)
// ---------------------------------------------------------------------------
__global__ void build_cells_kernel(const void* __restrict__ maskp) {
    __shared__ int s_float, s_byte;
    __shared__ int wsum[32];
    int tid = threadIdx.x;
    if (tid == 0) { s_float = 0; s_byte = 0; }
    __syncthreads();
    if (tid < 256) {
        unsigned w = ((const unsigned*)maskp)[tid];
        if (w == 0x3F800000u) atomicOr(&s_float, 1);
        else if (w > 1u)      atomicOr(&s_byte, 1);
    }
    __syncthreads();
    int active;
    if (s_float)      active = (((const float*)maskp)[tid] != 0.0f) ? 1 : 0;
    else if (s_byte)  active = (((const unsigned char*)maskp)[tid] != 0) ? 1 : 0;
    else              active = (((const int*)maskp)[tid] != 0) ? 1 : 0;

    unsigned bal = __ballot_sync(0xffffffffu, active);
    int lane = tid & 31, wid = tid >> 5;
    int pre = __popc(bal & ((1u << lane) - 1u));
    if (lane == 31) wsum[wid] = pre + active;
    __syncthreads();
    if (wid == 0) {
        int v = wsum[lane];
        #pragma unroll
        for (int off = 1; off < 32; off <<= 1) {
            int t = __shfl_up_sync(0xffffffffu, v, off);
            if (lane >= off) v += t;
        }
        wsum[lane] = v;
    }
    __syncthreads();
    int base = (wid == 0) ? 0 : wsum[wid - 1];
    if (active) g_cellList[base + pre] = tid;
    if (tid == 1023) g_cellCount = wsum[31];
}

// ---------------------------------------------------------------------------
// Kernel 0b: RNA-round MLP weights to tf32 once
// ---------------------------------------------------------------------------
__global__ void round_weights_kernel(const float* __restrict__ w1,
                                     const float* __restrict__ w2) {
    int i = blockIdx.x * 256 + threadIdx.x;
    if (i < CH * HID) {
        g_w1r[i] = tf32r(w1[i]);
        g_w2r[i] = tf32r(w2[i]);
    }
}

// ---------------------------------------------------------------------------
// Kernel 1: depthwise 7^3 conv on active cells.
// Block = (1 cell) x (4 channels = 2 pairs), 64 threads, 1 warp per pair.
// Same per-warp scheme as round 12 (2 y-rows per thread, dz 4-way split,
// register-cached weight rows); block halved -> 28.4 KB smem -> 8 blocks/SM
// for fine-grained stage/compute overlap across blocks.
// ---------------------------------------------------------------------------
#define CONV_TILE_F2 1220                          // 10 z-planes * 122
#define CONV_TILE_B  (2 * CONV_TILE_F2 * 8)        // 19520
#define CONV_WROW    10                            // padded f2 per weight row
#define CONV_WGT_B   (2 * 49 * CONV_WROW * 8)      // 7840
#define CONV_SOUT_B  (64 * 4 * 4)                  // 1024
#define CONV_SMEM    (CONV_TILE_B + CONV_WGT_B + CONV_SOUT_B)   // 28384

__global__ __launch_bounds__(64)
void conv_kernel(const float* __restrict__ x,
                 const float* __restrict__ dw_w,
                 const float* __restrict__ dw_b) {
    int cellSlot = blockIdx.x / 48;
    if (cellSlot >= g_cellCount) return;
    int pg   = blockIdx.x % 48;
    int cell = g_cellList[cellSlot];
    int b  = cell >> 9;
    int cz = (cell >> 6) & 7, cy = (cell >> 3) & 7, cx = cell & 7;
    int z0 = cz * 4, y0 = cy * 4, x0 = cx * 4;
    int c0 = pg * 4;

    extern __shared__ char sm[];
    float2* tile = (float2*)sm;                         // [2][10z][10y(12 slot)]
    float2* wgt  = (float2*)(sm + CONV_TILE_B);         // [2][49][10]
    float*  sOut = (float*)(sm + CONV_TILE_B + CONV_WGT_B);  // [64][4]

    int tid = threadIdx.x;
    const float* xb = x + (size_t)b * CH * SPAT;

    // ---- stage input (2 pairs x 10x10x10), packed float2 ----
    for (int idx = tid; idx < 2 * 1000; idx += 64) {
        int p  = idx / 1000;
        int s  = idx - p * 1000;
        int zi = s / 100;
        int r  = s - zi * 100;
        int yi = r / 10;
        int xi = r - yi * 10;
        int gz = z0 + zi - 3, gy = y0 + yi - 3, gx = x0 + xi - 3;
        float v0 = 0.f, v1 = 0.f;
        if (gz >= 0 && gz < DIM && gy >= 0 && gy < DIM && gx >= 0 && gx < DIM) {
            size_t off = (size_t)(c0 + 2 * p) * SPAT + gz * 1024 + gy * 32 + gx;
            v0 = xb[off];
            v1 = xb[off + SPAT];
        }
        tile[p * CONV_TILE_F2 + zi * 122 + yi * 12 + xi] = make_float2(v0, v1);
    }
    // ---- stage weights, rows padded to CONV_WROW float2 ----
    for (int idx = tid; idx < 2 * KV; idx += 64) {
        int p = idx / KV;
        int t = idx - p * KV;
        int row = t / 7, col = t - row * 7;
        wgt[p * 49 * CONV_WROW + row * CONV_WROW + col] =
            make_float2(dw_w[(c0 + 2 * p) * KV + t],
                        dw_w[(c0 + 2 * p + 1) * KV + t]);
    }
    __syncthreads();

    int p    = tid >> 5;        // pair 0..1 (warp id)
    int lane = tid & 31;
    int z    = (lane >> 3) & 3; // out z
    int yh   = (lane >> 2) & 1; // y half: outputs y = 2*yh, 2*yh+1
    int dzq  = lane & 3;        // dz quarter: dz in {dzq, dzq+4}
    int ybase = yh * 2;

    float2 aY0[4], aY1[4];
    #pragma unroll
    for (int i = 0; i < 4; i++) { aY0[i] = make_float2(0.f, 0.f); aY1[i] = make_float2(0.f, 0.f); }

    const float2* tp = tile + p * CONV_TILE_F2;
    const float2* wp = wgt + p * 49 * CONV_WROW;

    for (int it = 0; it < 2; it++) {
        int dz = dzq + it * 4;
        if (dz < 7) {
            const float2* zb  = tp + (z + dz) * 122;
            const float4* wdz = (const float4*)(wp + dz * 7 * CONV_WROW);
            float2 wrow[7];
            #pragma unroll
            for (int r = 0; r < 8; r++) {
                const float2* row = zb + (ybase + r) * 12;
                float4 q0 = *(const float4*)(row + 0);
                float4 q1 = *(const float4*)(row + 2);
                float4 q2 = *(const float4*)(row + 4);
                float4 q3 = *(const float4*)(row + 6);
                float4 q4 = *(const float4*)(row + 8);
                float2 rr[10];
                rr[0] = make_float2(q0.x, q0.y); rr[1] = make_float2(q0.z, q0.w);
                rr[2] = make_float2(q1.x, q1.y); rr[3] = make_float2(q1.z, q1.w);
                rr[4] = make_float2(q2.x, q2.y); rr[5] = make_float2(q2.z, q2.w);
                rr[6] = make_float2(q3.x, q3.y); rr[7] = make_float2(q3.z, q3.w);
                rr[8] = make_float2(q4.x, q4.y); rr[9] = make_float2(q4.z, q4.w);

                if (r >= 1) {
                    #pragma unroll
                    for (int dx = 0; dx < 7; dx++) {
                        float2 w = wrow[dx];
                        aY1[0] = ffma2(rr[dx + 0], w, aY1[0]);
                        aY1[1] = ffma2(rr[dx + 1], w, aY1[1]);
                        aY1[2] = ffma2(rr[dx + 2], w, aY1[2]);
                        aY1[3] = ffma2(rr[dx + 3], w, aY1[3]);
                    }
                }
                if (r < 7) {
                    const float4* wr4 = wdz + r * (CONV_WROW / 2);
                    float4 wa = wr4[0], wb = wr4[1], wc = wr4[2], wd = wr4[3];
                    wrow[0] = make_float2(wa.x, wa.y); wrow[1] = make_float2(wa.z, wa.w);
                    wrow[2] = make_float2(wb.x, wb.y); wrow[3] = make_float2(wb.z, wb.w);
                    wrow[4] = make_float2(wc.x, wc.y); wrow[5] = make_float2(wc.z, wc.w);
                    wrow[6] = make_float2(wd.x, wd.y);
                    #pragma unroll
                    for (int dx = 0; dx < 7; dx++) {
                        float2 w = wrow[dx];
                        aY0[0] = ffma2(rr[dx + 0], w, aY0[0]);
                        aY0[1] = ffma2(rr[dx + 1], w, aY0[1]);
                        aY0[2] = ffma2(rr[dx + 2], w, aY0[2]);
                        aY0[3] = ffma2(rr[dx + 3], w, aY0[3]);
                    }
                }
            }
        }
    }

    // ---- combine dz quarters (lane bits 0-1) ----
    #pragma unroll
    for (int i = 0; i < 4; i++) {
        aY0[i].x += __shfl_xor_sync(0xffffffffu, aY0[i].x, 1);
        aY0[i].y += __shfl_xor_sync(0xffffffffu, aY0[i].y, 1);
        aY1[i].x += __shfl_xor_sync(0xffffffffu, aY1[i].x, 1);
        aY1[i].y += __shfl_xor_sync(0xffffffffu, aY1[i].y, 1);
        aY0[i].x += __shfl_xor_sync(0xffffffffu, aY0[i].x, 2);
        aY0[i].y += __shfl_xor_sync(0xffffffffu, aY0[i].y, 2);
        aY1[i].x += __shfl_xor_sync(0xffffffffu, aY1[i].x, 2);
        aY1[i].y += __shfl_xor_sync(0xffffffffu, aY1[i].y, 2);
    }

    if (dzq == 0) {
        float bx = dw_b[c0 + 2 * p], by = dw_b[c0 + 2 * p + 1];
        int t0 = z * 16 + (ybase + 0) * 4;
        int t1 = z * 16 + (ybase + 1) * 4;
        #pragma unroll
        for (int xo = 0; xo < 4; xo++) {
            sOut[(t0 + xo) * 4 + 2 * p]     = aY0[xo].x + bx;
            sOut[(t0 + xo) * 4 + 2 * p + 1] = aY0[xo].y + by;
            sOut[(t1 + xo) * 4 + 2 * p]     = aY1[xo].x + bx;
            sOut[(t1 + xo) * 4 + 2 * p + 1] = aY1[xo].y + by;
        }
    }
    __syncthreads();

    // ---- write compacted channels-last: 64 tokens x 4 ch = 64 float4 ----
    {
        int tok = tid;          // 0..63
        float4 v = *(const float4*)&sOut[tok * 4];
        *(float4*)(g_yc + (size_t)cellSlot * CELLTOK * CH
                   + (size_t)tok * CH + c0) = v;
    }
}

// ---------------------------------------------------------------------------
// Kernel 2a: LN statistics only: g_yc -> g_stats (mu, rstd per token).
// ---------------------------------------------------------------------------
__global__ __launch_bounds__(256)
void stats_kernel() {
    int cellSlot = blockIdx.x;
    if (cellSlot >= g_cellCount) return;
    int tid = threadIdx.x;
    int row = tid >> 2, q = tid & 3;

    const float* yr = g_yc + (size_t)cellSlot * CELLTOK * CH + (size_t)row * CH + q * 48;

    float s = 0.f, ss = 0.f;
    #pragma unroll
    for (int i = 0; i < 12; i++) {
        float4 v = *(const float4*)(yr + i * 4);
        s  += v.x + v.y + v.z + v.w;
        ss += v.x * v.x + v.y * v.y + v.z * v.z + v.w * v.w;
    }
    s  += __shfl_xor_sync(0xffffffffu, s, 1);
    ss += __shfl_xor_sync(0xffffffffu, ss, 1);
    s  += __shfl_xor_sync(0xffffffffu, s, 2);
    ss += __shfl_xor_sync(0xffffffffu, ss, 2);
    if (q == 0) {
        float mu   = s * (1.0f / 192.0f);
        float var  = ss * (1.0f / 192.0f) - mu * mu;
        g_stats[cellSlot * CELLTOK + row] = make_float2(mu, rsqrtf(var + 1e-6f));
    }
}

// ---------------------------------------------------------------------------
// Kernel 2b: GEMM1 with fused LayerNorm on A + gelu -> g_h.
// Block = (cellSlot, quarter): M64 x N192 x K192. K chunks of 32.
// B double-buffered via cp.async; A software-double-buffered through regs
// (LDG early, LN-transform + STS after compute of previous chunk).
// smem unchanged: 69,632 B (3 blocks/SM).
// ---------------------------------------------------------------------------
#define SA2   36
#define SB2   200
#define SO2   197
#define M2_OFF_B (2 * 64 * SA2)
#define M2_SMEM ((M2_OFF_B + 2 * 32 * SB2) * 4)

__global__ __launch_bounds__(256)
void mlp1_kernel(const float* __restrict__ ln_w, const float* __restrict__ ln_b,
                 const float* __restrict__ bias1) {
    int cellSlot = blockIdx.x >> 2;
    if (cellSlot >= g_cellCount) return;
    int n0 = (blockIdx.x & 3) * 192;

    extern __shared__ float sm1[];
    float* sAb = sm1;
    float* sBb = sm1 + M2_OFF_B;

    int tid = threadIdx.x;
    const float* yrow = g_yc + (size_t)cellSlot * CELLTOK * CH;
    const float2* stats = g_stats + cellSlot * CELLTOK;
    const float* w1 = g_w1r;

    // thread's two A elements per chunk: i1 = tid, i2 = tid + 256
    int r1 = tid >> 3,           kq1 = tid & 7;
    int r2 = (tid + 256) >> 3,   kq2 = tid & 7;

    // ---- prologue: prefetch B(0), stage A(0) (LDG -> LN -> STS) ----
    for (int i = tid; i < 1536; i += 256) {
        int k = i / 48, q = i - k * 48;
        cp_async16(&sBb[k * SB2 + q * 4], w1 + (size_t)k * HID + n0 + q * 4);
    }
    CP_COMMIT();
    {
        float4 v1 = *(const float4*)(yrow + (size_t)r1 * CH + kq1 * 4);
        float4 v2 = *(const float4*)(yrow + (size_t)r2 * CH + kq2 * 4);
        float2 s1 = stats[r1], s2 = stats[r2];
        float4 w4 = *(const float4*)(ln_w + kq1 * 4);
        float4 b4 = *(const float4*)(ln_b + kq1 * 4);
        float4 t1, t2;
        t1.x = tf32r((v1.x - s1.x) * s1.y * w4.x + b4.x);
        t1.y = tf32r((v1.y - s1.x) * s1.y * w4.y + b4.y);
        t1.z = tf32r((v1.z - s1.x) * s1.y * w4.z + b4.z);
        t1.w = tf32r((v1.w - s1.x) * s1.y * w4.w + b4.w);
        t2.x = tf32r((v2.x - s2.x) * s2.y * w4.x + b4.x);
        t2.y = tf32r((v2.y - s2.x) * s2.y * w4.y + b4.y);
        t2.z = tf32r((v2.z - s2.x) * s2.y * w4.z + b4.z);
        t2.w = tf32r((v2.w - s2.x) * s2.y * w4.w + b4.w);
        *(float4*)&sAb[r1 * SA2 + kq1 * 4] = t1;
        *(float4*)&sAb[r2 * SA2 + kq2 * 4] = t2;
    }

    int wid = tid >> 5, lane = tid & 31;
    int g = lane >> 2, tg = lane & 3;
    int m0  = (wid >> 1) * 16;
    int nh2 = (wid & 1) * 96;

    float acc[12][4];
    #pragma unroll
    for (int s = 0; s < 12; s++)
        #pragma unroll
        for (int e = 0; e < 4; e++) acc[s][e] = 0.f;

    for (int kc = 0; kc < 6; kc++) {
        float4 v1, v2; float2 s1, s2; float4 w4, b4;
        bool more = (kc + 1 < 6);
        if (more) {
            int kb = (kc + 1) * 32;
            float* dB = sBb + ((kc + 1) & 1) * 32 * SB2;
            for (int i = tid; i < 1536; i += 256) {
                int k = i / 48, q = i - k * 48;
                cp_async16(&dB[k * SB2 + q * 4], w1 + (size_t)(kb + k) * HID + n0 + q * 4);
            }
            // early LDG of next A chunk (latency covered by compute below)
            v1 = *(const float4*)(yrow + (size_t)r1 * CH + kb + kq1 * 4);
            v2 = *(const float4*)(yrow + (size_t)r2 * CH + kb + kq2 * 4);
            s1 = stats[r1]; s2 = stats[r2];
            w4 = *(const float4*)(ln_w + kb + kq1 * 4);
            b4 = *(const float4*)(ln_b + kb + kq1 * 4);
        }
        CP_COMMIT();
        CP_WAIT1();
        __syncthreads();

        const float* sA = sAb + (kc & 1) * 64 * SA2;
        const float* sB = sBb + (kc & 1) * 32 * SB2;

        #pragma unroll
        for (int ks = 0; ks < 4; ks++) {
            int k0 = ks * 8;
            float av[4];
            av[0] = sA[(m0 + g) * SA2 + k0 + tg];
            av[1] = sA[(m0 + g + 8) * SA2 + k0 + tg];
            av[2] = sA[(m0 + g) * SA2 + k0 + tg + 4];
            av[3] = sA[(m0 + g + 8) * SA2 + k0 + tg + 4];
            #pragma unroll
            for (int sub = 0; sub < 12; sub++) {
                float bb0 = sB[(k0 + tg) * SB2 + nh2 + sub * 8 + g];
                float bb1 = sB[(k0 + tg + 4) * SB2 + nh2 + sub * 8 + g];
                mma_tf32(acc[sub], av, bb0, bb1);
            }
        }

        if (more) {
            float* dA = sAb + ((kc + 1) & 1) * 64 * SA2;
            float4 t1, t2;
            t1.x = tf32r((v1.x - s1.x) * s1.y * w4.x + b4.x);
            t1.y = tf32r((v1.y - s1.x) * s1.y * w4.y + b4.y);
            t1.z = tf32r((v1.z - s1.x) * s1.y * w4.z + b4.z);
            t1.w = tf32r((v1.w - s1.x) * s1.y * w4.w + b4.w);
            t2.x = tf32r((v2.x - s2.x) * s2.y * w4.x + b4.x);
            t2.y = tf32r((v2.y - s2.x) * s2.y * w4.y + b4.y);
            t2.z = tf32r((v2.z - s2.x) * s2.y * w4.z + b4.z);
            t2.w = tf32r((v2.w - s2.x) * s2.y * w4.w + b4.w);
            *(float4*)&dA[r1 * SA2 + kq1 * 4] = t1;
            *(float4*)&dA[r2 * SA2 + kq2 * 4] = t2;
        }
        __syncthreads();
    }

    float* hout = g_h + (size_t)cellSlot * CELLTOK * HID + n0;
    #pragma unroll
    for (int sub = 0; sub < 12; sub++) {
        int n = nh2 + sub * 8 + 2 * tg;
        float bb0 = __ldg(bias1 + n0 + n), bb1 = __ldg(bias1 + n0 + n + 1);
        float2 v0 = make_float2(tf32r(gelu_exact(acc[sub][0] + bb0)),
                                tf32r(gelu_exact(acc[sub][1] + bb1)));
        float2 v1 = make_float2(tf32r(gelu_exact(acc[sub][2] + bb0)),
                                tf32r(gelu_exact(acc[sub][3] + bb1)));
        *(float2*)&hout[(size_t)(m0 + g) * HID + n]     = v0;
        *(float2*)&hout[(size_t)(m0 + g + 8) * HID + n] = v1;
    }
}

// ---------------------------------------------------------------------------
// Kernel 3: GEMM2 + b2 + gamma -> dense NCDHW scatter (unchanged).
// ---------------------------------------------------------------------------
__global__ __launch_bounds__(256)
void mlp2_kernel(const float* __restrict__ bias2,
                 const float* __restrict__ gamma, float* __restrict__ out) {
    int cellSlot = blockIdx.x;
    if (cellSlot >= g_cellCount) return;
    int cell = g_cellList[cellSlot];
    int b  = cell >> 9;
    int cz = (cell >> 6) & 7, cy = (cell >> 3) & 7, cx = cell & 7;
    int z0 = cz * 4, y0 = cy * 4, x0 = cx * 4;

    extern __shared__ float sm2[];
    float* sAb = sm2;
    float* sBb = sm2 + M2_OFF_B;
    float* sO  = sm2 + M2_OFF_B;

    int tid = threadIdx.x;
    const float* hrow = g_h + (size_t)cellSlot * CELLTOK * HID;
    const float* w2 = g_w2r;

    {
        for (int i = tid; i < 512; i += 256) {
            int r = i >> 3, kq = i & 7;
            cp_async16(&sAb[r * SA2 + kq * 4], hrow + (size_t)r * HID + kq * 4);
        }
        for (int i = tid; i < 1536; i += 256) {
            int k = i / 48, q = i - k * 48;
            cp_async16(&sBb[k * SB2 + q * 4], w2 + (size_t)k * CH + q * 4);
        }
        CP_COMMIT();
    }

    int wid = tid >> 5, lane = tid & 31;
    int g = lane >> 2, tg = lane & 3;
    int m0  = (wid >> 1) * 16;
    int nh2 = (wid & 1) * 96;

    float acc[12][4];
    #pragma unroll
    for (int s = 0; s < 12; s++)
        #pragma unroll
        for (int e = 0; e < 4; e++) acc[s][e] = 0.f;

    for (int kc = 0; kc < 24; kc++) {
        if (kc + 1 < 24) {
            int kb = (kc + 1) * 32;
            float* dA = sAb + ((kc + 1) & 1) * 64 * SA2;
            float* dB = sBb + ((kc + 1) & 1) * 32 * SB2;
            for (int i = tid; i < 512; i += 256) {
                int r = i >> 3, kq = i & 7;
                cp_async16(&dA[r * SA2 + kq * 4], hrow + (size_t)r * HID + kb + kq * 4);
            }
            for (int i = tid; i < 1536; i += 256) {
                int k = i / 48, q = i - k * 48;
                cp_async16(&dB[k * SB2 + q * 4], w2 + (size_t)(kb + k) * CH + q * 4);
            }
        }
        CP_COMMIT();
        CP_WAIT1();
        __syncthreads();

        const float* sA = sAb + (kc & 1) * 64 * SA2;
        const float* sB = sBb + (kc & 1) * 32 * SB2;

        #pragma unroll
        for (int ks = 0; ks < 4; ks++) {
            int k0 = ks * 8;
            float av[4];
            av[0] = sA[(m0 + g) * SA2 + k0 + tg];
            av[1] = sA[(m0 + g + 8) * SA2 + k0 + tg];
            av[2] = sA[(m0 + g) * SA2 + k0 + tg + 4];
            av[3] = sA[(m0 + g + 8) * SA2 + k0 + tg + 4];
            #pragma unroll
            for (int sub = 0; sub < 12; sub++) {
                float bb0 = sB[(k0 + tg) * SB2 + nh2 + sub * 8 + g];
                float bb1 = sB[(k0 + tg + 4) * SB2 + nh2 + sub * 8 + g];
                mma_tf32(acc[sub], av, bb0, bb1);
            }
        }
        __syncthreads();
    }

    #pragma unroll
    for (int sub = 0; sub < 12; sub++) {
        int n = nh2 + sub * 8 + 2 * tg;
        float g0 = __ldg(gamma + n), g1 = __ldg(gamma + n + 1);
        float bb0 = __ldg(bias2 + n), bb1 = __ldg(bias2 + n + 1);
        sO[(m0 + g) * SO2 + n]         = g0 * (acc[sub][0] + bb0);
        sO[(m0 + g) * SO2 + n + 1]     = g1 * (acc[sub][1] + bb1);
        sO[(m0 + g + 8) * SO2 + n]     = g0 * (acc[sub][2] + bb0);
        sO[(m0 + g + 8) * SO2 + n + 1] = g1 * (acc[sub][3] + bb1);
    }
    __syncthreads();

    for (int i = tid; i < 3072; i += 256) {
        int c = i >> 4, r = i & 15;
        int z = r >> 2, y = r & 3;
        int tok = z * 16 + y * 4;
        float4 v;
        v.x = sO[(tok + 0) * SO2 + c];
        v.y = sO[(tok + 1) * SO2 + c];
        v.z = sO[(tok + 2) * SO2 + c];
        v.w = sO[(tok + 3) * SO2 + c];
        size_t off = ((size_t)(b * CH + c)) * SPAT + (size_t)(z0 + z) * 1024
                   + (size_t)(y0 + y) * 32 + x0;
        *(float4*)(out + off) = v;
    }
}

// ---------------------------------------------------------------------------
// Launch
// ---------------------------------------------------------------------------
extern "C" void kernel_launch(void* const* d_in, const int* in_sizes, int n_in,
                              void* d_out, int out_size) {
    const float* x     = (const float*)d_in[0];
    const void*  mask  = d_in[1];
    const float* dw_w  = (const float*)d_in[2];
    const float* dw_b  = (const float*)d_in[3];
    const float* ln_w  = (const float*)d_in[4];
    const float* ln_b  = (const float*)d_in[5];
    const float* w1    = (const float*)d_in[6];
    const float* b1    = (const float*)d_in[7];
    const float* w2    = (const float*)d_in[8];
    const float* b2    = (const float*)d_in[9];
    const float* gamma = (const float*)d_in[10];
    float* out = (float*)d_out;

    cudaFuncSetAttribute(conv_kernel, cudaFuncAttributeMaxDynamicSharedMemorySize, CONV_SMEM);
    cudaFuncSetAttribute(mlp1_kernel, cudaFuncAttributeMaxDynamicSharedMemorySize, M2_SMEM);
    cudaFuncSetAttribute(mlp2_kernel, cudaFuncAttributeMaxDynamicSharedMemorySize, M2_SMEM);

    cudaMemsetAsync(d_out, 0, (size_t)out_size * sizeof(float));
    build_cells_kernel<<<1, 1024>>>(mask);
    round_weights_kernel<<<(CH * HID + 255) / 256, 256>>>(w1, w2);
    conv_kernel<<<NCELLS * 48, 64, CONV_SMEM>>>(x, dw_w, dw_b);
    stats_kernel<<<NCELLS, 256>>>();
    mlp1_kernel<<<NCELLS * 4, 256, M2_SMEM>>>(ln_w, ln_b, b1);
    mlp2_kernel<<<NCELLS, 256, M2_SMEM>>>(b2, gamma, out);
}

// round 14
// speedup vs baseline: 1.2391x; 1.2391x over previous
#include <cuda_runtime.h>
#include <cuda_bf16.h>
#include <math.h>
#include <stdint.h>

// ---------------------------------------------------------------------------
// Problem constants
// ---------------------------------------------------------------------------
#define BATCH   2
#define CH      192
#define DIM     32
#define SPAT    (DIM*DIM*DIM)      // 32768
#define HID     768
#define KS      7
#define KV      343
#define NCELLS  1024               // 2 * 8*8*8
#define CELLTOK 64                 // 4*4*4

// ---------------------------------------------------------------------------
// Device scratch (static globals -- no runtime allocation)
// ---------------------------------------------------------------------------
__device__ int    g_cellList[NCELLS];
__device__ int    g_cellCount;
__device__ float  g_yc[(size_t)NCELLS * CELLTOK * CH];    // compacted conv out
__device__ float  g_ln[(size_t)NCELLS * CELLTOK * CH];    // LN'd (tf32) tokens
__device__ float  g_h [(size_t)NCELLS * CELLTOK * HID];   // hidden activations
__device__ float  g_w1r[CH * HID];                        // tf32-rounded w1
__device__ float  g_w2r[HID * CH];                        // tf32-rounded w2
__device__ float2 g_xp[(size_t)192 * SPAT];               // pair-packed x
__device__ float2 g_wp[96 * 49 * 10];                     // pair-packed dw_w

// ---------------------------------------------------------------------------
// Helpers
// ---------------------------------------------------------------------------
__device__ __forceinline__ float2 ffma2(float2 a, float2 b, float2 c) {
    union U { float2 f; unsigned long long u; };
    U A, B, C, D;
    A.f = a; B.f = b; C.f = c;
    asm("fma.rn.f32x2 %0, %1, %2, %3;" : "=l"(D.u) : "l"(A.u), "l"(B.u), "l"(C.u));
    return D.f;
}

__device__ __forceinline__ float tf32r(float x) {
    unsigned int u;
    asm("cvt.rna.tf32.f32 %0, %1;" : "=r"(u) : "f"(x));
    return __uint_as_float(u);
}

// mma.sync m16n8k8 tf32: d += a * b   (mapping verified by passing rounds)
__device__ __forceinline__ void mma_tf32(float* d, const float* a, float b0, float b1) {
    asm volatile(
        "mma.sync.aligned.m16n8k8.row.col.f32.tf32.tf32.f32 "
        "{%0,%1,%2,%3}, {%4,%5,%6,%7}, {%8,%9}, {%0,%1,%2,%3};"
        : "+f"(d[0]), "+f"(d[1]), "+f"(d[2]), "+f"(d[3])
        : "r"(__float_as_uint(a[0])), "r"(__float_as_uint(a[1])),
          "r"(__float_as_uint(a[2])), "r"(__float_as_uint(a[3])),
          "r"(__float_as_uint(b0)),   "r"(__float_as_uint(b1)));
}

__device__ __forceinline__ float gelu_exact(float x) {
    return 0.5f * x * (1.0f + erff(x * 0.70710678118654752f));
}

__device__ __forceinline__ void cp_async16(void* smem_dst, const void* gmem_src) {
    unsigned s = (unsigned)__cvta_generic_to_shared(smem_dst);
    asm volatile("cp.async.cg.shared.global [%0], [%1], 16;\n" :: "r"(s), "l"(gmem_src));
}
__device__ __forceinline__ void cp_async16_zf(void* smem_dst, const void* gmem_src, int srcbytes) {
    unsigned s = (unsigned)__cvta_generic_to_shared(smem_dst);
    asm volatile("cp.async.ca.shared.global [%0], [%1], 16, %2;\n"
                 :: "r"(s), "l"(gmem_src), "r"(srcbytes));
}
#define CP_COMMIT() asm volatile("cp.async.commit_group;\n" ::: "memory")
#define CP_WAIT1()  asm volatile("cp.async.wait_group 1;\n" ::: "memory")
#define CP_WAIT0()  asm volatile("cp.async.wait_group 0;\n" ::: "memory")

// ---------------------------------------------------------------------------
// Kernel 0a: build compacted active-cell list (dtype-sniffing)
// ---------------------------------------------------------------------------
__global__ void build_cells_kernel(const void* __restrict__ maskp) {
    __shared__ int s_float, s_byte;
    __shared__ int wsum[32];
    int tid = threadIdx.x;
    if (tid == 0) { s_float = 0; s_byte = 0; }
    __syncthreads();
    if (tid < 256) {
        unsigned w = ((const unsigned*)maskp)[tid];
        if (w == 0x3F800000u) atomicOr(&s_float, 1);
        else if (w > 1u)      atomicOr(&s_byte, 1);
    }
    __syncthreads();
    int active;
    if (s_float)      active = (((const float*)maskp)[tid] != 0.0f) ? 1 : 0;
    else if (s_byte)  active = (((const unsigned char*)maskp)[tid] != 0) ? 1 : 0;
    else              active = (((const int*)maskp)[tid] != 0) ? 1 : 0;

    unsigned bal = __ballot_sync(0xffffffffu, active);
    int lane = tid & 31, wid = tid >> 5;
    int pre = __popc(bal & ((1u << lane) - 1u));
    if (lane == 31) wsum[wid] = pre + active;
    __syncthreads();
    if (wid == 0) {
        int v = wsum[lane];
        #pragma unroll
        for (int off = 1; off < 32; off <<= 1) {
            int t = __shfl_up_sync(0xffffffffu, v, off);
            if (lane >= off) v += t;
        }
        wsum[lane] = v;
    }
    __syncthreads();
    int base = (wid == 0) ? 0 : wsum[wid - 1];
    if (active) g_cellList[base + pre] = tid;
    if (tid == 1023) g_cellCount = wsum[31];
}

// ---------------------------------------------------------------------------
// Kernel 0b: RNA-round MLP weights to tf32 once
// ---------------------------------------------------------------------------
__global__ void round_weights_kernel(const float* __restrict__ w1,
                                     const float* __restrict__ w2) {
    int i = blockIdx.x * 256 + threadIdx.x;
    if (i < CH * HID) {
        g_w1r[i] = tf32r(w1[i]);
        g_w2r[i] = tf32r(w2[i]);
    }
}

// ---------------------------------------------------------------------------
// Kernel 0c: pack x into channel-pair float2 planes g_xp[b*96+pr][z][y][x]
// ---------------------------------------------------------------------------
__global__ void pack_x_kernel(const float* __restrict__ x) {
    size_t i = (size_t)blockIdx.x * 256 + threadIdx.x;
    if (i < (size_t)192 * SPAT) {
        size_t pr = i / SPAT;            // 0..191 (= b*96 + pair)
        size_t s  = i - pr * SPAT;
        size_t b  = pr / 96, pp = pr - b * 96;
        const float* base = x + (b * CH + pp * 2) * (size_t)SPAT + s;
        g_xp[i] = make_float2(base[0], base[SPAT]);
    }
}

// ---------------------------------------------------------------------------
// Kernel 0d: pack dw_w into conv smem layout g_wp[pair][49 rows][10 f2]
// ---------------------------------------------------------------------------
__global__ void pack_w_kernel(const float* __restrict__ dw_w) {
    int i = blockIdx.x * 256 + threadIdx.x;
    if (i < 96 * KV) {
        int pr = i / KV, t = i - pr * KV;
        int row = t / 7, col = t - row * 7;
        g_wp[pr * 490 + row * 10 + col] =
            make_float2(dw_w[(2 * pr) * KV + t], dw_w[(2 * pr + 1) * KV + t]);
    }
}

// ---------------------------------------------------------------------------
// Kernel 1: depthwise 7^3 conv on active cells (round-12 compute layout,
// cp.async staging from pre-packed g_xp / g_wp).
// Block = (1 cell) x (8 channels = 4 pairs), 128 threads, 1 warp per pair.
// x window = [x0-4, x0+8) (12 f2, all 16B chunks aligned, whole-chunk OOB).
// ---------------------------------------------------------------------------
#define CONV_TILE_F2 1220                          // 10 z-planes * 122
#define CONV_TILE_B  (4 * CONV_TILE_F2 * 8)        // 39040
#define CONV_WROW    10
#define CONV_WGT_B   (4 * 490 * 8)                 // 15680
#define CONV_SOUT_B  (64 * 8 * 4)                  // 2048
#define CONV_SMEM    (CONV_TILE_B + CONV_WGT_B + CONV_SOUT_B)   // 56768

__global__ __launch_bounds__(128)
void conv_kernel(const float* __restrict__ dw_b) {
    int cellSlot = blockIdx.x / 24;
    if (cellSlot >= g_cellCount) return;
    int pg   = blockIdx.x % 24;
    int cell = g_cellList[cellSlot];
    int b  = cell >> 9;
    int cz = (cell >> 6) & 7, cy = (cell >> 3) & 7, cx = cell & 7;
    int z0 = cz * 4, y0 = cy * 4, x0 = cx * 4;
    int c0 = pg * 8;

    extern __shared__ char sm[];
    float2* tile = (float2*)sm;                         // [4][10z][10y(12 slot)]
    float2* wgt  = (float2*)(sm + CONV_TILE_B);         // [4][49][10]
    float*  sOut = (float*)(sm + CONV_TILE_B + CONV_WGT_B);  // [64][8]

    int tid = threadIdx.x;
    int prBase = b * 96 + pg * 4;

    // ---- stage input via cp.async: 4 pairs x 10z x 10y x 6 chunks ----
    for (int idx = tid; idx < 2400; idx += 128) {
        int k  = idx % 6;
        int t  = idx / 6;
        int yi = t % 10;
        int t2 = t / 10;
        int zi = t2 % 10;
        int p  = t2 / 10;
        int gz = z0 + zi - 3, gy = y0 + yi - 3, gxc = x0 - 4 + 2 * k;
        bool ok = ((unsigned)gz < 32u) && ((unsigned)gy < 32u)
               && (gxc >= 0) && (gxc <= 30);
        const float2* src = g_xp + (size_t)(prBase + p) * SPAT
                          + (ok ? (gz * 1024 + gy * 32 + gxc) : 0);
        cp_async16_zf(&tile[p * CONV_TILE_F2 + zi * 122 + yi * 12 + 2 * k],
                      src, ok ? 16 : 0);
    }
    // ---- stage weights via cp.async: 4 pairs x 245 chunks ----
    for (int idx = tid; idx < 980; idx += 128) {
        int p = idx / 245, j = idx % 245;
        cp_async16(&wgt[p * 490 + j * 2], g_wp + (pg * 4 + p) * 490 + j * 2);
    }
    CP_COMMIT();
    CP_WAIT0();
    __syncthreads();

    int p    = tid >> 5;        // pair 0..3 (warp id)
    int lane = tid & 31;
    int z    = (lane >> 3) & 3; // out z
    int yh   = (lane >> 2) & 1; // y half: outputs y = 2*yh, 2*yh+1
    int dzq  = lane & 3;        // dz quarter: dz in {dzq, dzq+4}
    int ybase = yh * 2;

    float2 aY0[4], aY1[4];
    #pragma unroll
    for (int i = 0; i < 4; i++) { aY0[i] = make_float2(0.f, 0.f); aY1[i] = make_float2(0.f, 0.f); }

    const float2* tp = tile + p * CONV_TILE_F2;
    const float2* wp = wgt + p * 490;

    for (int it = 0; it < 2; it++) {
        int dz = dzq + it * 4;
        if (dz < 7) {
            const float2* zb  = tp + (z + dz) * 122;
            const float4* wdz = (const float4*)(wp + dz * 7 * CONV_WROW);
            float2 wrow[7];
            #pragma unroll
            for (int r = 0; r < 8; r++) {
                const float2* row = zb + (ybase + r) * 12;
                float4 q0 = *(const float4*)(row + 0);
                float4 q1 = *(const float4*)(row + 2);
                float4 q2 = *(const float4*)(row + 4);
                float4 q3 = *(const float4*)(row + 6);
                float4 q4 = *(const float4*)(row + 8);
                float4 q5 = *(const float4*)(row + 10);
                float2 rr[12];
                rr[0]  = make_float2(q0.x, q0.y); rr[1]  = make_float2(q0.z, q0.w);
                rr[2]  = make_float2(q1.x, q1.y); rr[3]  = make_float2(q1.z, q1.w);
                rr[4]  = make_float2(q2.x, q2.y); rr[5]  = make_float2(q2.z, q2.w);
                rr[6]  = make_float2(q3.x, q3.y); rr[7]  = make_float2(q3.z, q3.w);
                rr[8]  = make_float2(q4.x, q4.y); rr[9]  = make_float2(q4.z, q4.w);
                rr[10] = make_float2(q5.x, q5.y); rr[11] = make_float2(q5.z, q5.w);

                if (r >= 1) {      // y1 uses previous weight row (dy = r-1)
                    #pragma unroll
                    for (int dx = 0; dx < 7; dx++) {
                        float2 w = wrow[dx];
                        aY1[0] = ffma2(rr[dx + 1], w, aY1[0]);
                        aY1[1] = ffma2(rr[dx + 2], w, aY1[1]);
                        aY1[2] = ffma2(rr[dx + 3], w, aY1[2]);
                        aY1[3] = ffma2(rr[dx + 4], w, aY1[3]);
                    }
                }
                if (r < 7) {       // load weight row (dz, r), use for y0 (dy = r)
                    const float4* wr4 = wdz + r * (CONV_WROW / 2);
                    float4 wa = wr4[0], wb = wr4[1], wc = wr4[2], wd = wr4[3];
                    wrow[0] = make_float2(wa.x, wa.y); wrow[1] = make_float2(wa.z, wa.w);
                    wrow[2] = make_float2(wb.x, wb.y); wrow[3] = make_float2(wb.z, wb.w);
                    wrow[4] = make_float2(wc.x, wc.y); wrow[5] = make_float2(wc.z, wc.w);
                    wrow[6] = make_float2(wd.x, wd.y);
                    #pragma unroll
                    for (int dx = 0; dx < 7; dx++) {
                        float2 w = wrow[dx];
                        aY0[0] = ffma2(rr[dx + 1], w, aY0[0]);
                        aY0[1] = ffma2(rr[dx + 2], w, aY0[1]);
                        aY0[2] = ffma2(rr[dx + 3], w, aY0[2]);
                        aY0[3] = ffma2(rr[dx + 4], w, aY0[3]);
                    }
                }
            }
        }
    }

    // ---- combine dz quarters (lane bits 0-1) ----
    #pragma unroll
    for (int i = 0; i < 4; i++) {
        aY0[i].x += __shfl_xor_sync(0xffffffffu, aY0[i].x, 1);
        aY0[i].y += __shfl_xor_sync(0xffffffffu, aY0[i].y, 1);
        aY1[i].x += __shfl_xor_sync(0xffffffffu, aY1[i].x, 1);
        aY1[i].y += __shfl_xor_sync(0xffffffffu, aY1[i].y, 1);
        aY0[i].x += __shfl_xor_sync(0xffffffffu, aY0[i].x, 2);
        aY0[i].y += __shfl_xor_sync(0xffffffffu, aY0[i].y, 2);
        aY1[i].x += __shfl_xor_sync(0xffffffffu, aY1[i].x, 2);
        aY1[i].y += __shfl_xor_sync(0xffffffffu, aY1[i].y, 2);
    }

    if (dzq == 0) {
        float bx = dw_b[c0 + 2 * p], by = dw_b[c0 + 2 * p + 1];
        int t0 = z * 16 + (ybase + 0) * 4;
        int t1 = z * 16 + (ybase + 1) * 4;
        #pragma unroll
        for (int xo = 0; xo < 4; xo++) {
            sOut[(t0 + xo) * 8 + 2 * p]     = aY0[xo].x + bx;
            sOut[(t0 + xo) * 8 + 2 * p + 1] = aY0[xo].y + by;
            sOut[(t1 + xo) * 8 + 2 * p]     = aY1[xo].x + bx;
            sOut[(t1 + xo) * 8 + 2 * p + 1] = aY1[xo].y + by;
        }
    }
    __syncthreads();

    // ---- write compacted channels-last: 64 tokens x 8 ch = 128 float4 ----
    {
        int tok  = tid >> 1;
        int half = tid & 1;
        float4 v = *(const float4*)&sOut[tok * 8 + half * 4];
        *(float4*)(g_yc + (size_t)cellSlot * CELLTOK * CH
                   + (size_t)tok * CH + c0 + half * 4) = v;
    }
}

// ---------------------------------------------------------------------------
// Kernel 2a: standalone LayerNorm: g_yc -> g_ln (tf32-rounded).
// ---------------------------------------------------------------------------
__global__ __launch_bounds__(256)
void ln_kernel(const float* __restrict__ ln_w, const float* __restrict__ ln_b) {
    int cellSlot = blockIdx.x;
    if (cellSlot >= g_cellCount) return;
    int tid = threadIdx.x;
    int row = tid >> 2, q = tid & 3;

    const float* yr = g_yc + (size_t)cellSlot * CELLTOK * CH + (size_t)row * CH + q * 48;
    float*       lr = g_ln + (size_t)cellSlot * CELLTOK * CH + (size_t)row * CH + q * 48;

    float v[48];
    #pragma unroll
    for (int i = 0; i < 12; i++)
        *(float4*)&v[i * 4] = *(const float4*)(yr + i * 4);

    float s = 0.f, ss = 0.f;
    #pragma unroll
    for (int i = 0; i < 48; i++) { s += v[i]; ss += v[i] * v[i]; }
    s  += __shfl_xor_sync(0xffffffffu, s, 1);
    ss += __shfl_xor_sync(0xffffffffu, ss, 1);
    s  += __shfl_xor_sync(0xffffffffu, s, 2);
    ss += __shfl_xor_sync(0xffffffffu, ss, 2);
    float mu   = s * (1.0f / 192.0f);
    float var  = ss * (1.0f / 192.0f) - mu * mu;
    float rstd = rsqrtf(var + 1e-6f);

    #pragma unroll
    for (int i = 0; i < 48; i++) {
        int c = q * 48 + i;
        v[i] = tf32r((v[i] - mu) * rstd * __ldg(ln_w + c) + __ldg(ln_b + c));
    }
    #pragma unroll
    for (int i = 0; i < 12; i++)
        *(float4*)(lr + i * 4) = *(const float4*)&v[i * 4];
}

// ---------------------------------------------------------------------------
// Kernel 2b: GEMM1 (mlp2-clone) + gelu -> g_h.   (round-12 version)
// ---------------------------------------------------------------------------
#define SA2   36
#define SB2   200
#define SO2   197
#define M2_OFF_B (2 * 64 * SA2)
#define M2_SMEM ((M2_OFF_B + 2 * 32 * SB2) * 4)

__global__ __launch_bounds__(256)
void mlp1_kernel(const float* __restrict__ bias1) {
    int cellSlot = blockIdx.x >> 2;
    if (cellSlot >= g_cellCount) return;
    int n0 = (blockIdx.x & 3) * 192;

    extern __shared__ float sm1[];
    float* sAb = sm1;
    float* sBb = sm1 + M2_OFF_B;

    int tid = threadIdx.x;
    const float* lnrow = g_ln + (size_t)cellSlot * CELLTOK * CH;
    const float* w1 = g_w1r;

    {
        for (int i = tid; i < 512; i += 256) {
            int r = i >> 3, kq = i & 7;
            cp_async16(&sAb[r * SA2 + kq * 4], lnrow + (size_t)r * CH + kq * 4);
        }
        for (int i = tid; i < 1536; i += 256) {
            int k = i / 48, q = i - k * 48;
            cp_async16(&sBb[k * SB2 + q * 4], w1 + (size_t)k * HID + n0 + q * 4);
        }
        CP_COMMIT();
    }

    int wid = tid >> 5, lane = tid & 31;
    int g = lane >> 2, tg = lane & 3;
    int m0  = (wid >> 1) * 16;
    int nh2 = (wid & 1) * 96;

    float acc[12][4];
    #pragma unroll
    for (int s = 0; s < 12; s++)
        #pragma unroll
        for (int e = 0; e < 4; e++) acc[s][e] = 0.f;

    for (int kc = 0; kc < 6; kc++) {
        if (kc + 1 < 6) {
            int kb = (kc + 1) * 32;
            float* dA = sAb + ((kc + 1) & 1) * 64 * SA2;
            float* dB = sBb + ((kc + 1) & 1) * 32 * SB2;
            for (int i = tid; i < 512; i += 256) {
                int r = i >> 3, kq = i & 7;
                cp_async16(&dA[r * SA2 + kq * 4], lnrow + (size_t)r * CH + kb + kq * 4);
            }
            for (int i = tid; i < 1536; i += 256) {
                int k = i / 48, q = i - k * 48;
                cp_async16(&dB[k * SB2 + q * 4], w1 + (size_t)(kb + k) * HID + n0 + q * 4);
            }
        }
        CP_COMMIT();
        CP_WAIT1();
        __syncthreads();

        const float* sA = sAb + (kc & 1) * 64 * SA2;
        const float* sB = sBb + (kc & 1) * 32 * SB2;

        #pragma unroll
        for (int ks = 0; ks < 4; ks++) {
            int k0 = ks * 8;
            float av[4];
            av[0] = sA[(m0 + g) * SA2 + k0 + tg];
            av[1] = sA[(m0 + g + 8) * SA2 + k0 + tg];
            av[2] = sA[(m0 + g) * SA2 + k0 + tg + 4];
            av[3] = sA[(m0 + g + 8) * SA2 + k0 + tg + 4];
            #pragma unroll
            for (int sub = 0; sub < 12; sub++) {
                float bb0 = sB[(k0 + tg) * SB2 + nh2 + sub * 8 + g];
                float bb1 = sB[(k0 + tg + 4) * SB2 + nh2 + sub * 8 + g];
                mma_tf32(acc[sub], av, bb0, bb1);
            }
        }
        __syncthreads();
    }

    float* hout = g_h + (size_t)cellSlot * CELLTOK * HID + n0;
    #pragma unroll
    for (int sub = 0; sub < 12; sub++) {
        int n = nh2 + sub * 8 + 2 * tg;
        float bb0 = __ldg(bias1 + n0 + n), bb1 = __ldg(bias1 + n0 + n + 1);
        float2 v0 = make_float2(tf32r(gelu_exact(acc[sub][0] + bb0)),
                                tf32r(gelu_exact(acc[sub][1] + bb1)));
        float2 v1 = make_float2(tf32r(gelu_exact(acc[sub][2] + bb0)),
                                tf32r(gelu_exact(acc[sub][3] + bb1)));
        *(float2*)&hout[(size_t)(m0 + g) * HID + n]     = v0;
        *(float2*)&hout[(size_t)(m0 + g + 8) * HID + n] = v1;
    }
}

// ---------------------------------------------------------------------------
// Kernel 3: GEMM2 + b2 + gamma -> dense NCDHW scatter (unchanged).
// ---------------------------------------------------------------------------
__global__ __launch_bounds__(256)
void mlp2_kernel(const float* __restrict__ bias2,
                 const float* __restrict__ gamma, float* __restrict__ out) {
    int cellSlot = blockIdx.x;
    if (cellSlot >= g_cellCount) return;
    int cell = g_cellList[cellSlot];
    int b  = cell >> 9;
    int cz = (cell >> 6) & 7, cy = (cell >> 3) & 7, cx = cell & 7;
    int z0 = cz * 4, y0 = cy * 4, x0 = cx * 4;

    extern __shared__ float sm2[];
    float* sAb = sm2;
    float* sBb = sm2 + M2_OFF_B;
    float* sO  = sm2 + M2_OFF_B;

    int tid = threadIdx.x;
    const float* hrow = g_h + (size_t)cellSlot * CELLTOK * HID;
    const float* w2 = g_w2r;

    {
        for (int i = tid; i < 512; i += 256) {
            int r = i >> 3, kq = i & 7;
            cp_async16(&sAb[r * SA2 + kq * 4], hrow + (size_t)r * HID + kq * 4);
        }
        for (int i = tid; i < 1536; i += 256) {
            int k = i / 48, q = i - k * 48;
            cp_async16(&sBb[k * SB2 + q * 4], w2 + (size_t)k * CH + q * 4);
        }
        CP_COMMIT();
    }

    int wid = tid >> 5, lane = tid & 31;
    int g = lane >> 2, tg = lane & 3;
    int m0  = (wid >> 1) * 16;
    int nh2 = (wid & 1) * 96;

    float acc[12][4];
    #pragma unroll
    for (int s = 0; s < 12; s++)
        #pragma unroll
        for (int e = 0; e < 4; e++) acc[s][e] = 0.f;

    for (int kc = 0; kc < 24; kc++) {
        if (kc + 1 < 24) {
            int kb = (kc + 1) * 32;
            float* dA = sAb + ((kc + 1) & 1) * 64 * SA2;
            float* dB = sBb + ((kc + 1) & 1) * 32 * SB2;
            for (int i = tid; i < 512; i += 256) {
                int r = i >> 3, kq = i & 7;
                cp_async16(&dA[r * SA2 + kq * 4], hrow + (size_t)r * HID + kb + kq * 4);
            }
            for (int i = tid; i < 1536; i += 256) {
                int k = i / 48, q = i - k * 48;
                cp_async16(&dB[k * SB2 + q * 4], w2 + (size_t)(kb + k) * CH + q * 4);
            }
        }
        CP_COMMIT();
        CP_WAIT1();
        __syncthreads();

        const float* sA = sAb + (kc & 1) * 64 * SA2;
        const float* sB = sBb + (kc & 1) * 32 * SB2;

        #pragma unroll
        for (int ks = 0; ks < 4; ks++) {
            int k0 = ks * 8;
            float av[4];
            av[0] = sA[(m0 + g) * SA2 + k0 + tg];
            av[1] = sA[(m0 + g + 8) * SA2 + k0 + tg];
            av[2] = sA[(m0 + g) * SA2 + k0 + tg + 4];
            av[3] = sA[(m0 + g + 8) * SA2 + k0 + tg + 4];
            #pragma unroll
            for (int sub = 0; sub < 12; sub++) {
                float bb0 = sB[(k0 + tg) * SB2 + nh2 + sub * 8 + g];
                float bb1 = sB[(k0 + tg + 4) * SB2 + nh2 + sub * 8 + g];
                mma_tf32(acc[sub], av, bb0, bb1);
            }
        }
        __syncthreads();
    }

    #pragma unroll
    for (int sub = 0; sub < 12; sub++) {
        int n = nh2 + sub * 8 + 2 * tg;
        float g0 = __ldg(gamma + n), g1 = __ldg(gamma + n + 1);
        float bb0 = __ldg(bias2 + n), bb1 = __ldg(bias2 + n + 1);
        sO[(m0 + g) * SO2 + n]         = g0 * (acc[sub][0] + bb0);
        sO[(m0 + g) * SO2 + n + 1]     = g1 * (acc[sub][1] + bb1);
        sO[(m0 + g + 8) * SO2 + n]     = g0 * (acc[sub][2] + bb0);
        sO[(m0 + g + 8) * SO2 + n + 1] = g1 * (acc[sub][3] + bb1);
    }
    __syncthreads();

    for (int i = tid; i < 3072; i += 256) {
        int c = i >> 4, r = i & 15;
        int z = r >> 2, y = r & 3;
        int tok = z * 16 + y * 4;
        float4 v;
        v.x = sO[(tok + 0) * SO2 + c];
        v.y = sO[(tok + 1) * SO2 + c];
        v.z = sO[(tok + 2) * SO2 + c];
        v.w = sO[(tok + 3) * SO2 + c];
        size_t off = ((size_t)(b * CH + c)) * SPAT + (size_t)(z0 + z) * 1024
                   + (size_t)(y0 + y) * 32 + x0;
        *(float4*)(out + off) = v;
    }
}

// ---------------------------------------------------------------------------
// Launch
// ---------------------------------------------------------------------------
extern "C" void kernel_launch(void* const* d_in, const int* in_sizes, int n_in,
                              void* d_out, int out_size) {
    const float* x     = (const float*)d_in[0];
    const void*  mask  = d_in[1];
    const float* dw_w  = (const float*)d_in[2];
    const float* dw_b  = (const float*)d_in[3];
    const float* ln_w  = (const float*)d_in[4];
    const float* ln_b  = (const float*)d_in[5];
    const float* w1    = (const float*)d_in[6];
    const float* b1    = (const float*)d_in[7];
    const float* w2    = (const float*)d_in[8];
    const float* b2    = (const float*)d_in[9];
    const float* gamma = (const float*)d_in[10];
    float* out = (float*)d_out;

    cudaFuncSetAttribute(conv_kernel, cudaFuncAttributeMaxDynamicSharedMemorySize, CONV_SMEM);
    cudaFuncSetAttribute(mlp1_kernel, cudaFuncAttributeMaxDynamicSharedMemorySize, M2_SMEM);
    cudaFuncSetAttribute(mlp2_kernel, cudaFuncAttributeMaxDynamicSharedMemorySize, M2_SMEM);

    cudaMemsetAsync(d_out, 0, (size_t)out_size * sizeof(float));
    build_cells_kernel<<<1, 1024>>>(mask);
    round_weights_kernel<<<(CH * HID + 255) / 256, 256>>>(w1, w2);
    pack_x_kernel<<<(int)(((size_t)192 * SPAT + 255) / 256), 256>>>(x);
    pack_w_kernel<<<(96 * KV + 255) / 256, 256>>>(dw_w);
    conv_kernel<<<NCELLS * 24, 128, CONV_SMEM>>>(dw_b);
    ln_kernel<<<NCELLS, 256>>>(ln_w, ln_b);
    mlp1_kernel<<<NCELLS * 4, 256, M2_SMEM>>>(b1);
    mlp2_kernel<<<NCELLS, 256, M2_SMEM>>>(b2, gamma, out);
}

// round 15
// speedup vs baseline: 1.2434x; 1.0035x over previous
#include <cuda_runtime.h>
#include <cuda_bf16.h>
#include <math.h>
#include <stdint.h>

// ---------------------------------------------------------------------------
// Problem constants
// ---------------------------------------------------------------------------
#define BATCH   2
#define CH      192
#define DIM     32
#define SPAT    (DIM*DIM*DIM)      // 32768
#define HID     768
#define KS      7
#define KV      343
#define NCELLS  1024               // 2 * 8*8*8
#define CELLTOK 64                 // 4*4*4

// ---------------------------------------------------------------------------
// Device scratch (static globals -- no runtime allocation)
// ---------------------------------------------------------------------------
__device__ int    g_cellList[NCELLS];
__device__ int    g_cellCount;
__device__ float  g_yc[(size_t)NCELLS * CELLTOK * CH];    // compacted conv out
__device__ float  g_ln[(size_t)NCELLS * CELLTOK * CH];    // LN'd (tf32) tokens
__device__ float  g_h [(size_t)NCELLS * CELLTOK * HID];   // hidden activations
__device__ float  g_w1r[CH * HID];                        // tf32-rounded w1
__device__ float  g_w2r[HID * CH];                        // tf32-rounded w2
__device__ float2 g_xp[(size_t)192 * SPAT];               // pair-packed x
__device__ float2 g_wp[96 * 49 * 10];                     // pair-packed dw_w

// ---------------------------------------------------------------------------
// Helpers
// ---------------------------------------------------------------------------
__device__ __forceinline__ float2 ffma2(float2 a, float2 b, float2 c) {
    union U { float2 f; unsigned long long u; };
    U A, B, C, D;
    A.f = a; B.f = b; C.f = c;
    asm("fma.rn.f32x2 %0, %1, %2, %3;" : "=l"(D.u) : "l"(A.u), "l"(B.u), "l"(C.u));
    return D.f;
}

__device__ __forceinline__ float tf32r(float x) {
    unsigned int u;
    asm("cvt.rna.tf32.f32 %0, %1;" : "=r"(u) : "f"(x));
    return __uint_as_float(u);
}

// mma.sync m16n8k8 tf32: d += a * b   (mapping verified by passing rounds)
__device__ __forceinline__ void mma_tf32(float* d, const float* a, float b0, float b1) {
    asm volatile(
        "mma.sync.aligned.m16n8k8.row.col.f32.tf32.tf32.f32 "
        "{%0,%1,%2,%3}, {%4,%5,%6,%7}, {%8,%9}, {%0,%1,%2,%3};"
        : "+f"(d[0]), "+f"(d[1]), "+f"(d[2]), "+f"(d[3])
        : "r"(__float_as_uint(a[0])), "r"(__float_as_uint(a[1])),
          "r"(__float_as_uint(a[2])), "r"(__float_as_uint(a[3])),
          "r"(__float_as_uint(b0)),   "r"(__float_as_uint(b1)));
}

__device__ __forceinline__ float gelu_exact(float x) {
    return 0.5f * x * (1.0f + erff(x * 0.70710678118654752f));
}

__device__ __forceinline__ void cp_async16(void* smem_dst, const void* gmem_src) {
    unsigned s = (unsigned)__cvta_generic_to_shared(smem_dst);
    asm volatile("cp.async.cg.shared.global [%0], [%1], 16;\n" :: "r"(s), "l"(gmem_src));
}
__device__ __forceinline__ void cp_async16_zf(void* smem_dst, const void* gmem_src, int srcbytes) {
    unsigned s = (unsigned)__cvta_generic_to_shared(smem_dst);
    asm volatile("cp.async.ca.shared.global [%0], [%1], 16, %2;\n"
                 :: "r"(s), "l"(gmem_src), "r"(srcbytes));
}
#define CP_COMMIT() asm volatile("cp.async.commit_group;\n" ::: "memory")
#define CP_WAIT1()  asm volatile("cp.async.wait_group 1;\n" ::: "memory")
#define CP_WAIT0()  asm volatile("cp.async.wait_group 0;\n" ::: "memory")

// ---------------------------------------------------------------------------
// Kernel 0a: build compacted active-cell list (dtype-sniffing)
// ---------------------------------------------------------------------------
__global__ void build_cells_kernel(const void* __restrict__ maskp) {
    __shared__ int s_float, s_byte;
    __shared__ int wsum[32];
    int tid = threadIdx.x;
    if (tid == 0) { s_float = 0; s_byte = 0; }
    __syncthreads();
    if (tid < 256) {
        unsigned w = ((const unsigned*)maskp)[tid];
        if (w == 0x3F800000u) atomicOr(&s_float, 1);
        else if (w > 1u)      atomicOr(&s_byte, 1);
    }
    __syncthreads();
    int active;
    if (s_float)      active = (((const float*)maskp)[tid] != 0.0f) ? 1 : 0;
    else if (s_byte)  active = (((const unsigned char*)maskp)[tid] != 0) ? 1 : 0;
    else              active = (((const int*)maskp)[tid] != 0) ? 1 : 0;

    unsigned bal = __ballot_sync(0xffffffffu, active);
    int lane = tid & 31, wid = tid >> 5;
    int pre = __popc(bal & ((1u << lane) - 1u));
    if (lane == 31) wsum[wid] = pre + active;
    __syncthreads();
    if (wid == 0) {
        int v = wsum[lane];
        #pragma unroll
        for (int off = 1; off < 32; off <<= 1) {
            int t = __shfl_up_sync(0xffffffffu, v, off);
            if (lane >= off) v += t;
        }
        wsum[lane] = v;
    }
    __syncthreads();
    int base = (wid == 0) ? 0 : wsum[wid - 1];
    if (active) g_cellList[base + pre] = tid;
    if (tid == 1023) g_cellCount = wsum[31];
}

// ---------------------------------------------------------------------------
// Kernel 0b: RNA-round MLP weights to tf32 once
// ---------------------------------------------------------------------------
__global__ void round_weights_kernel(const float* __restrict__ w1,
                                     const float* __restrict__ w2) {
    int i = blockIdx.x * 256 + threadIdx.x;
    if (i < CH * HID) {
        g_w1r[i] = tf32r(w1[i]);
        g_w2r[i] = tf32r(w2[i]);
    }
}

// ---------------------------------------------------------------------------
// Kernel 0c: pack x into channel-pair float2 planes g_xp[b*96+pr][z][y][x]
// ---------------------------------------------------------------------------
__global__ void pack_x_kernel(const float* __restrict__ x) {
    size_t i = (size_t)blockIdx.x * 256 + threadIdx.x;
    if (i < (size_t)192 * SPAT) {
        size_t pr = i / SPAT;            // 0..191 (= b*96 + pair)
        size_t s  = i - pr * SPAT;
        size_t b  = pr / 96, pp = pr - b * 96;
        const float* base = x + (b * CH + pp * 2) * (size_t)SPAT + s;
        g_xp[i] = make_float2(base[0], base[SPAT]);
    }
}

// ---------------------------------------------------------------------------
// Kernel 0d: pack dw_w into conv layout g_wp[pair][49 rows][10 f2]
// ---------------------------------------------------------------------------
__global__ void pack_w_kernel(const float* __restrict__ dw_w) {
    int i = blockIdx.x * 256 + threadIdx.x;
    if (i < 96 * KV) {
        int pr = i / KV, t = i - pr * KV;
        int row = t / 7, col = t - row * 7;
        g_wp[pr * 490 + row * 10 + col] =
            make_float2(dw_w[(2 * pr) * KV + t], dw_w[(2 * pr + 1) * KV + t]);
    }
}

// ---------------------------------------------------------------------------
// Kernel 1: depthwise 7^3 conv on active cells.
// cp.async tile staging from pre-packed g_xp; weights read directly from
// g_wp via __ldg float4 (L1-broadcast: row depends only on (pair,dz,r);
// 4 distinct 16B addresses per warp-load). smem 41.1 KB -> 5 blocks/SM.
// ---------------------------------------------------------------------------
#define CONV_TILE_F2 1220                          // 10 z-planes * 122
#define CONV_TILE_B  (4 * CONV_TILE_F2 * 8)        // 39040
#define CONV_SOUT_B  (64 * 8 * 4)                  // 2048
#define CONV_SMEM    (CONV_TILE_B + CONV_SOUT_B)   // 41088

__global__ __launch_bounds__(128)
void conv_kernel(const float* __restrict__ dw_b) {
    int cellSlot = blockIdx.x / 24;
    if (cellSlot >= g_cellCount) return;
    int pg   = blockIdx.x % 24;
    int cell = g_cellList[cellSlot];
    int b  = cell >> 9;
    int cz = (cell >> 6) & 7, cy = (cell >> 3) & 7, cx = cell & 7;
    int z0 = cz * 4, y0 = cy * 4, x0 = cx * 4;
    int c0 = pg * 8;

    extern __shared__ char sm[];
    float2* tile = (float2*)sm;                         // [4][10z][10y(12 slot)]
    float*  sOut = (float*)(sm + CONV_TILE_B);          // [64][8]

    int tid = threadIdx.x;
    int prBase = b * 96 + pg * 4;

    // ---- stage input via cp.async: 4 pairs x 10z x 10y x 6 chunks ----
    for (int idx = tid; idx < 2400; idx += 128) {
        int k  = idx % 6;
        int t  = idx / 6;
        int yi = t % 10;
        int t2 = t / 10;
        int zi = t2 % 10;
        int p  = t2 / 10;
        int gz = z0 + zi - 3, gy = y0 + yi - 3, gxc = x0 - 4 + 2 * k;
        bool ok = ((unsigned)gz < 32u) && ((unsigned)gy < 32u)
               && (gxc >= 0) && (gxc <= 30);
        const float2* src = g_xp + (size_t)(prBase + p) * SPAT
                          + (ok ? (gz * 1024 + gy * 32 + gxc) : 0);
        cp_async16_zf(&tile[p * CONV_TILE_F2 + zi * 122 + yi * 12 + 2 * k],
                      src, ok ? 16 : 0);
    }
    CP_COMMIT();
    CP_WAIT0();
    __syncthreads();

    int p    = tid >> 5;        // pair 0..3 (warp id)
    int lane = tid & 31;
    int z    = (lane >> 3) & 3; // out z
    int yh   = (lane >> 2) & 1; // y half: outputs y = 2*yh, 2*yh+1
    int dzq  = lane & 3;        // dz quarter: dz in {dzq, dzq+4}
    int ybase = yh * 2;

    float2 aY0[4], aY1[4];
    #pragma unroll
    for (int i = 0; i < 4; i++) { aY0[i] = make_float2(0.f, 0.f); aY1[i] = make_float2(0.f, 0.f); }

    const float2* tp = tile + p * CONV_TILE_F2;
    const float2* wp = g_wp + (size_t)(pg * 4 + p) * 490;

    for (int it = 0; it < 2; it++) {
        int dz = dzq + it * 4;
        if (dz < 7) {
            const float2* zb  = tp + (z + dz) * 122;
            const float4* wdz = (const float4*)(wp + dz * 7 * 10);   // 16B-aligned
            float2 wrow[7];
            #pragma unroll
            for (int r = 0; r < 8; r++) {
                const float2* row = zb + (ybase + r) * 12;
                float4 q0 = *(const float4*)(row + 0);
                float4 q1 = *(const float4*)(row + 2);
                float4 q2 = *(const float4*)(row + 4);
                float4 q3 = *(const float4*)(row + 6);
                float4 q4 = *(const float4*)(row + 8);
                float4 q5 = *(const float4*)(row + 10);
                float2 rr[12];
                rr[0]  = make_float2(q0.x, q0.y); rr[1]  = make_float2(q0.z, q0.w);
                rr[2]  = make_float2(q1.x, q1.y); rr[3]  = make_float2(q1.z, q1.w);
                rr[4]  = make_float2(q2.x, q2.y); rr[5]  = make_float2(q2.z, q2.w);
                rr[6]  = make_float2(q3.x, q3.y); rr[7]  = make_float2(q3.z, q3.w);
                rr[8]  = make_float2(q4.x, q4.y); rr[9]  = make_float2(q4.z, q4.w);
                rr[10] = make_float2(q5.x, q5.y); rr[11] = make_float2(q5.z, q5.w);

                if (r >= 1) {      // y1 uses previous weight row (dy = r-1)
                    #pragma unroll
                    for (int dx = 0; dx < 7; dx++) {
                        float2 w = wrow[dx];
                        aY1[0] = ffma2(rr[dx + 1], w, aY1[0]);
                        aY1[1] = ffma2(rr[dx + 2], w, aY1[1]);
                        aY1[2] = ffma2(rr[dx + 3], w, aY1[2]);
                        aY1[3] = ffma2(rr[dx + 4], w, aY1[3]);
                    }
                }
                if (r < 7) {       // load weight row (dz, r) from gmem (L1)
                    int rbase = r * 5;       // row = 10 f2 = 5 f4
                    float4 wa = __ldg(wdz + rbase + 0);
                    float4 wb = __ldg(wdz + rbase + 1);
                    float4 wc = __ldg(wdz + rbase + 2);
                    float4 wd = __ldg(wdz + rbase + 3);
                    wrow[0] = make_float2(wa.x, wa.y); wrow[1] = make_float2(wa.z, wa.w);
                    wrow[2] = make_float2(wb.x, wb.y); wrow[3] = make_float2(wb.z, wb.w);
                    wrow[4] = make_float2(wc.x, wc.y); wrow[5] = make_float2(wc.z, wc.w);
                    wrow[6] = make_float2(wd.x, wd.y);
                    #pragma unroll
                    for (int dx = 0; dx < 7; dx++) {
                        float2 w = wrow[dx];
                        aY0[0] = ffma2(rr[dx + 1], w, aY0[0]);
                        aY0[1] = ffma2(rr[dx + 2], w, aY0[1]);
                        aY0[2] = ffma2(rr[dx + 3], w, aY0[2]);
                        aY0[3] = ffma2(rr[dx + 4], w, aY0[3]);
                    }
                }
            }
        }
    }

    // ---- combine dz quarters (lane bits 0-1) ----
    #pragma unroll
    for (int i = 0; i < 4; i++) {
        aY0[i].x += __shfl_xor_sync(0xffffffffu, aY0[i].x, 1);
        aY0[i].y += __shfl_xor_sync(0xffffffffu, aY0[i].y, 1);
        aY1[i].x += __shfl_xor_sync(0xffffffffu, aY1[i].x, 1);
        aY1[i].y += __shfl_xor_sync(0xffffffffu, aY1[i].y, 1);
        aY0[i].x += __shfl_xor_sync(0xffffffffu, aY0[i].x, 2);
        aY0[i].y += __shfl_xor_sync(0xffffffffu, aY0[i].y, 2);
        aY1[i].x += __shfl_xor_sync(0xffffffffu, aY1[i].x, 2);
        aY1[i].y += __shfl_xor_sync(0xffffffffu, aY1[i].y, 2);
    }

    if (dzq == 0) {
        float bx = dw_b[c0 + 2 * p], by = dw_b[c0 + 2 * p + 1];
        int t0 = z * 16 + (ybase + 0) * 4;
        int t1 = z * 16 + (ybase + 1) * 4;
        #pragma unroll
        for (int xo = 0; xo < 4; xo++) {
            sOut[(t0 + xo) * 8 + 2 * p]     = aY0[xo].x + bx;
            sOut[(t0 + xo) * 8 + 2 * p + 1] = aY0[xo].y + by;
            sOut[(t1 + xo) * 8 + 2 * p]     = aY1[xo].x + bx;
            sOut[(t1 + xo) * 8 + 2 * p + 1] = aY1[xo].y + by;
        }
    }
    __syncthreads();

    // ---- write compacted channels-last: 64 tokens x 8 ch = 128 float4 ----
    {
        int tok  = tid >> 1;
        int half = tid & 1;
        float4 v = *(const float4*)&sOut[tok * 8 + half * 4];
        *(float4*)(g_yc + (size_t)cellSlot * CELLTOK * CH
                   + (size_t)tok * CH + c0 + half * 4) = v;
    }
}

// ---------------------------------------------------------------------------
// Kernel 2a: standalone LayerNorm: g_yc -> g_ln (tf32-rounded).
// ---------------------------------------------------------------------------
__global__ __launch_bounds__(256)
void ln_kernel(const float* __restrict__ ln_w, const float* __restrict__ ln_b) {
    int cellSlot = blockIdx.x;
    if (cellSlot >= g_cellCount) return;
    int tid = threadIdx.x;
    int row = tid >> 2, q = tid & 3;

    const float* yr = g_yc + (size_t)cellSlot * CELLTOK * CH + (size_t)row * CH + q * 48;
    float*       lr = g_ln + (size_t)cellSlot * CELLTOK * CH + (size_t)row * CH + q * 48;

    float v[48];
    #pragma unroll
    for (int i = 0; i < 12; i++)
        *(float4*)&v[i * 4] = *(const float4*)(yr + i * 4);

    float s = 0.f, ss = 0.f;
    #pragma unroll
    for (int i = 0; i < 48; i++) { s += v[i]; ss += v[i] * v[i]; }
    s  += __shfl_xor_sync(0xffffffffu, s, 1);
    ss += __shfl_xor_sync(0xffffffffu, ss, 1);
    s  += __shfl_xor_sync(0xffffffffu, s, 2);
    ss += __shfl_xor_sync(0xffffffffu, ss, 2);
    float mu   = s * (1.0f / 192.0f);
    float var  = ss * (1.0f / 192.0f) - mu * mu;
    float rstd = rsqrtf(var + 1e-6f);

    #pragma unroll
    for (int i = 0; i < 48; i++) {
        int c = q * 48 + i;
        v[i] = tf32r((v[i] - mu) * rstd * __ldg(ln_w + c) + __ldg(ln_b + c));
    }
    #pragma unroll
    for (int i = 0; i < 12; i++)
        *(float4*)(lr + i * 4) = *(const float4*)&v[i * 4];
}

// ---------------------------------------------------------------------------
// Kernel 2b: GEMM1 (mlp2-clone) + gelu -> g_h.
// ---------------------------------------------------------------------------
#define SA2   36
#define SB2   200
#define SO2   197
#define M2_OFF_B (2 * 64 * SA2)
#define M2_SMEM ((M2_OFF_B + 2 * 32 * SB2) * 4)

__global__ __launch_bounds__(256)
void mlp1_kernel(const float* __restrict__ bias1) {
    int cellSlot = blockIdx.x >> 2;
    if (cellSlot >= g_cellCount) return;
    int n0 = (blockIdx.x & 3) * 192;

    extern __shared__ float sm1[];
    float* sAb = sm1;
    float* sBb = sm1 + M2_OFF_B;

    int tid = threadIdx.x;
    const float* lnrow = g_ln + (size_t)cellSlot * CELLTOK * CH;
    const float* w1 = g_w1r;

    {
        for (int i = tid; i < 512; i += 256) {
            int r = i >> 3, kq = i & 7;
            cp_async16(&sAb[r * SA2 + kq * 4], lnrow + (size_t)r * CH + kq * 4);
        }
        for (int i = tid; i < 1536; i += 256) {
            int k = i / 48, q = i - k * 48;
            cp_async16(&sBb[k * SB2 + q * 4], w1 + (size_t)k * HID + n0 + q * 4);
        }
        CP_COMMIT();
    }

    int wid = tid >> 5, lane = tid & 31;
    int g = lane >> 2, tg = lane & 3;
    int m0  = (wid >> 1) * 16;
    int nh2 = (wid & 1) * 96;

    float acc[12][4];
    #pragma unroll
    for (int s = 0; s < 12; s++)
        #pragma unroll
        for (int e = 0; e < 4; e++) acc[s][e] = 0.f;

    for (int kc = 0; kc < 6; kc++) {
        if (kc + 1 < 6) {
            int kb = (kc + 1) * 32;
            float* dA = sAb + ((kc + 1) & 1) * 64 * SA2;
            float* dB = sBb + ((kc + 1) & 1) * 32 * SB2;
            for (int i = tid; i < 512; i += 256) {
                int r = i >> 3, kq = i & 7;
                cp_async16(&dA[r * SA2 + kq * 4], lnrow + (size_t)r * CH + kb + kq * 4);
            }
            for (int i = tid; i < 1536; i += 256) {
                int k = i / 48, q = i - k * 48;
                cp_async16(&dB[k * SB2 + q * 4], w1 + (size_t)(kb + k) * HID + n0 + q * 4);
            }
        }
        CP_COMMIT();
        CP_WAIT1();
        __syncthreads();

        const float* sA = sAb + (kc & 1) * 64 * SA2;
        const float* sB = sBb + (kc & 1) * 32 * SB2;

        #pragma unroll
        for (int ks = 0; ks < 4; ks++) {
            int k0 = ks * 8;
            float av[4];
            av[0] = sA[(m0 + g) * SA2 + k0 + tg];
            av[1] = sA[(m0 + g + 8) * SA2 + k0 + tg];
            av[2] = sA[(m0 + g) * SA2 + k0 + tg + 4];
            av[3] = sA[(m0 + g + 8) * SA2 + k0 + tg + 4];
            #pragma unroll
            for (int sub = 0; sub < 12; sub++) {
                float bb0 = sB[(k0 + tg) * SB2 + nh2 + sub * 8 + g];
                float bb1 = sB[(k0 + tg + 4) * SB2 + nh2 + sub * 8 + g];
                mma_tf32(acc[sub], av, bb0, bb1);
            }
        }
        __syncthreads();
    }

    float* hout = g_h + (size_t)cellSlot * CELLTOK * HID + n0;
    #pragma unroll
    for (int sub = 0; sub < 12; sub++) {
        int n = nh2 + sub * 8 + 2 * tg;
        float bb0 = __ldg(bias1 + n0 + n), bb1 = __ldg(bias1 + n0 + n + 1);
        float2 v0 = make_float2(tf32r(gelu_exact(acc[sub][0] + bb0)),
                                tf32r(gelu_exact(acc[sub][1] + bb1)));
        float2 v1 = make_float2(tf32r(gelu_exact(acc[sub][2] + bb0)),
                                tf32r(gelu_exact(acc[sub][3] + bb1)));
        *(float2*)&hout[(size_t)(m0 + g) * HID + n]     = v0;
        *(float2*)&hout[(size_t)(m0 + g + 8) * HID + n] = v1;
    }
}

// ---------------------------------------------------------------------------
// Kernel 3: GEMM2 + b2 + gamma -> dense NCDHW scatter (unchanged).
// ---------------------------------------------------------------------------
__global__ __launch_bounds__(256)
void mlp2_kernel(const float* __restrict__ bias2,
                 const float* __restrict__ gamma, float* __restrict__ out) {
    int cellSlot = blockIdx.x;
    if (cellSlot >= g_cellCount) return;
    int cell = g_cellList[cellSlot];
    int b  = cell >> 9;
    int cz = (cell >> 6) & 7, cy = (cell >> 3) & 7, cx = cell & 7;
    int z0 = cz * 4, y0 = cy * 4, x0 = cx * 4;

    extern __shared__ float sm2[];
    float* sAb = sm2;
    float* sBb = sm2 + M2_OFF_B;
    float* sO  = sm2 + M2_OFF_B;

    int tid = threadIdx.x;
    const float* hrow = g_h + (size_t)cellSlot * CELLTOK * HID;
    const float* w2 = g_w2r;

    {
        for (int i = tid; i < 512; i += 256) {
            int r = i >> 3, kq = i & 7;
            cp_async16(&sAb[r * SA2 + kq * 4], hrow + (size_t)r * HID + kq * 4);
        }
        for (int i = tid; i < 1536; i += 256) {
            int k = i / 48, q = i - k * 48;
            cp_async16(&sBb[k * SB2 + q * 4], w2 + (size_t)k * CH + q * 4);
        }
        CP_COMMIT();
    }

    int wid = tid >> 5, lane = tid & 31;
    int g = lane >> 2, tg = lane & 3;
    int m0  = (wid >> 1) * 16;
    int nh2 = (wid & 1) * 96;

    float acc[12][4];
    #pragma unroll
    for (int s = 0; s < 12; s++)
        #pragma unroll
        for (int e = 0; e < 4; e++) acc[s][e] = 0.f;

    for (int kc = 0; kc < 24; kc++) {
        if (kc + 1 < 24) {
            int kb = (kc + 1) * 32;
            float* dA = sAb + ((kc + 1) & 1) * 64 * SA2;
            float* dB = sBb + ((kc + 1) & 1) * 32 * SB2;
            for (int i = tid; i < 512; i += 256) {
                int r = i >> 3, kq = i & 7;
                cp_async16(&dA[r * SA2 + kq * 4], hrow + (size_t)r * HID + kb + kq * 4);
            }
            for (int i = tid; i < 1536; i += 256) {
                int k = i / 48, q = i - k * 48;
                cp_async16(&dB[k * SB2 + q * 4], w2 + (size_t)(kb + k) * CH + q * 4);
            }
        }
        CP_COMMIT();
        CP_WAIT1();
        __syncthreads();

        const float* sA = sAb + (kc & 1) * 64 * SA2;
        const float* sB = sBb + (kc & 1) * 32 * SB2;

        #pragma unroll
        for (int ks = 0; ks < 4; ks++) {
            int k0 = ks * 8;
            float av[4];
            av[0] = sA[(m0 + g) * SA2 + k0 + tg];
            av[1] = sA[(m0 + g + 8) * SA2 + k0 + tg];
            av[2] = sA[(m0 + g) * SA2 + k0 + tg + 4];
            av[3] = sA[(m0 + g + 8) * SA2 + k0 + tg + 4];
            #pragma unroll
            for (int sub = 0; sub < 12; sub++) {
                float bb0 = sB[(k0 + tg) * SB2 + nh2 + sub * 8 + g];
                float bb1 = sB[(k0 + tg + 4) * SB2 + nh2 + sub * 8 + g];
                mma_tf32(acc[sub], av, bb0, bb1);
            }
        }
        __syncthreads();
    }

    #pragma unroll
    for (int sub = 0; sub < 12; sub++) {
        int n = nh2 + sub * 8 + 2 * tg;
        float g0 = __ldg(gamma + n), g1 = __ldg(gamma + n + 1);
        float bb0 = __ldg(bias2 + n), bb1 = __ldg(bias2 + n + 1);
        sO[(m0 + g) * SO2 + n]         = g0 * (acc[sub][0] + bb0);
        sO[(m0 + g) * SO2 + n + 1]     = g1 * (acc[sub][1] + bb1);
        sO[(m0 + g + 8) * SO2 + n]     = g0 * (acc[sub][2] + bb0);
        sO[(m0 + g + 8) * SO2 + n + 1] = g1 * (acc[sub][3] + bb1);
    }
    __syncthreads();

    for (int i = tid; i < 3072; i += 256) {
        int c = i >> 4, r = i & 15;
        int z = r >> 2, y = r & 3;
        int tok = z * 16 + y * 4;
        float4 v;
        v.x = sO[(tok + 0) * SO2 + c];
        v.y = sO[(tok + 1) * SO2 + c];
        v.z = sO[(tok + 2) * SO2 + c];
        v.w = sO[(tok + 3) * SO2 + c];
        size_t off = ((size_t)(b * CH + c)) * SPAT + (size_t)(z0 + z) * 1024
                   + (size_t)(y0 + y) * 32 + x0;
        *(float4*)(out + off) = v;
    }
}

// ---------------------------------------------------------------------------
// Launch
// ---------------------------------------------------------------------------
extern "C" void kernel_launch(void* const* d_in, const int* in_sizes, int n_in,
                              void* d_out, int out_size) {
    const float* x     = (const float*)d_in[0];
    const void*  mask  = d_in[1];
    const float* dw_w  = (const float*)d_in[2];
    const float* dw_b  = (const float*)d_in[3];
    const float* ln_w  = (const float*)d_in[4];
    const float* ln_b  = (const float*)d_in[5];
    const float* w1    = (const float*)d_in[6];
    const float* b1    = (const float*)d_in[7];
    const float* w2    = (const float*)d_in[8];
    const float* b2    = (const float*)d_in[9];
    const float* gamma = (const float*)d_in[10];
    float* out = (float*)d_out;

    cudaFuncSetAttribute(conv_kernel, cudaFuncAttributeMaxDynamicSharedMemorySize, CONV_SMEM);
    cudaFuncSetAttribute(mlp1_kernel, cudaFuncAttributeMaxDynamicSharedMemorySize, M2_SMEM);
    cudaFuncSetAttribute(mlp2_kernel, cudaFuncAttributeMaxDynamicSharedMemorySize, M2_SMEM);

    cudaMemsetAsync(d_out, 0, (size_t)out_size * sizeof(float));
    build_cells_kernel<<<1, 1024>>>(mask);
    round_weights_kernel<<<(CH * HID + 255) / 256, 256>>>(w1, w2);
    pack_x_kernel<<<(int)(((size_t)192 * SPAT + 255) / 256), 256>>>(x);
    pack_w_kernel<<<(96 * KV + 255) / 256, 256>>>(dw_w);
    conv_kernel<<<NCELLS * 24, 128, CONV_SMEM>>>(dw_b);
    ln_kernel<<<NCELLS, 256>>>(ln_w, ln_b);
    mlp1_kernel<<<NCELLS * 4, 256, M2_SMEM>>>(b1);
    mlp2_kernel<<<NCELLS, 256, M2_SMEM>>>(b2, gamma, out);
}